// round 12
// baseline (speedup 1.0000x reference)
#include <cuda_runtime.h>
#include <cuda_fp16.h>
#include <stdint.h>

// ---------------------------------------------------------------------------
// DiagonalElman on GB300 (base sm_103 ISA: mma.sync fp16 + ldmatrix + cp.async)
// R11: single-__syncthreads mainloop (CUTLASS order) in gemm_1t.
//  Wc = rn16(W_x) @ (W_in^T hi+lo) [2-term, 64x64 tiles],
//  fused [x_proj|xw] = x@[Wi|Wc]^T (1-term fp16, fp16 out, 3-stage pipeline),
//  segmented-parallel recurrence, output = cell @ W_out^T (1-term fp16).
//  h_final at d_out + B*T*D.
// ---------------------------------------------------------------------------

#define MAX_BTD (8 * 2048 * 1024)
#define MAX_DD  (1024 * 1024)

__device__ __half g_wide[2 * MAX_BTD];        // fp16 [M,2048]: 0-1023 xp, 1024-2047 xw
__device__ __half g_xh[MAX_BTD];              // x as fp16
__device__ __half g_ch[MAX_BTD];              // cell_out as fp16
__device__ __half g_wfuse[2 * MAX_DD];        // [2048,1024]: rows 0-1023 Wi, 1024-2047 Wc
__device__ __half g_wxh[MAX_DD];              // rn16(W_x)
__device__ __half g_with[MAX_DD], g_witl[MAX_DD];   // split of W_in^T
__device__ __half g_woh[MAX_DD];

// ============================ helpers =======================================
__device__ __forceinline__ uint32_t smem_u32(const void* p) {
    uint32_t a;
    asm("{ .reg .u64 t; cvta.to.shared.u64 t, %1; cvt.u32.u64 %0, t; }"
        : "=r"(a) : "l"(p));
    return a;
}
#define SWZ(x) ((x) ^ (((x) >> 3) & 0x70))

// mega elementwise prep: one 1D grid covering 4 jobs by index range
__global__ __launch_bounds__(256) void prep_mega(
    const float* __restrict__ x, const float* __restrict__ W_x,
    const float* __restrict__ W_out, const float* __restrict__ W_in,
    __half* __restrict__ xh, __half* __restrict__ wxh,
    __half* __restrict__ woh, __half* __restrict__ wfuse,
    int nx4, int w4) {
    int i = blockIdx.x * blockDim.x + threadIdx.x;
    const float* src;
    __half* dst;
    int j;
    if (i < nx4)                      { src = x;     dst = xh;    j = i; }
    else if (i < nx4 + w4)            { src = W_x;   dst = wxh;   j = i - nx4; }
    else if (i < nx4 + 2 * w4)        { src = W_out; dst = woh;   j = i - nx4 - w4; }
    else if (i < nx4 + 3 * w4)        { src = W_in;  dst = wfuse; j = i - nx4 - 2 * w4; }
    else return;
    float4 v = ((const float4*)src)[j];
    __half h[4] = {__float2half_rn(v.x), __float2half_rn(v.y),
                   __float2half_rn(v.z), __float2half_rn(v.w)};
    ((uint64_t*)dst)[j] = *(const uint64_t*)h;
}

// transpose fp32 [R,C] and emit fp16 hi/lo split of the transpose
__global__ __launch_bounds__(256) void wsplit_t_kernel(
    const float* __restrict__ src, __half* __restrict__ hi,
    __half* __restrict__ lo, int R, int C) {
    __shared__ float tile[32][33];
    int bx = blockIdx.x * 32, by = blockIdx.y * 32;
    int tx = threadIdx.x & 31, ty8 = threadIdx.x >> 5;
#pragma unroll
    for (int r = 0; r < 32; r += 8) {
        int row = by + ty8 + r, col = bx + tx;
        if (row < R && col < C) tile[ty8 + r][tx] = src[(size_t)row * C + col];
    }
    __syncthreads();
#pragma unroll
    for (int r = 0; r < 32; r += 8) {
        int row = bx + ty8 + r, col = by + tx;
        if (row < C && col < R) {
            float v = tile[tx][ty8 + r];
            __half h = __float2half_rn(v);
            __half l = __float2half_rn(v - __half2float(h));
            hi[(size_t)row * R + col] = h;
            lo[(size_t)row * R + col] = l;
        }
    }
}

// ============================ GEMM common ===================================
#define BKB 128                       // bytes per smem row (64 fp16)
#define TILE_B (128 * BKB)            // 16 KB per 128x64 tile

__device__ __forceinline__ void cp16(uint32_t dst, const void* src) {
    asm volatile("cp.async.cg.shared.global [%0], [%1], 16;" :: "r"(dst), "l"(src));
}
__device__ __forceinline__ void ldsm4(uint32_t* r, uint32_t addr) {
    asm volatile("ldmatrix.sync.aligned.m8n8.x4.shared.b16 {%0,%1,%2,%3}, [%4];"
                 : "=r"(r[0]), "=r"(r[1]), "=r"(r[2]), "=r"(r[3]) : "r"(addr));
}
__device__ __forceinline__ void mma16816(float* c, const uint32_t* a, uint32_t b0, uint32_t b1) {
    asm volatile(
        "mma.sync.aligned.m16n8k16.row.col.f32.f16.f16.f32 "
        "{%0,%1,%2,%3}, {%4,%5,%6,%7}, {%8,%9}, {%0,%1,%2,%3};"
        : "+f"(c[0]), "+f"(c[1]), "+f"(c[2]), "+f"(c[3])
        : "r"(a[0]), "r"(a[1]), "r"(a[2]), "r"(a[3]), "r"(b0), "r"(b1));
}

__device__ __forceinline__ void load_tile(uint32_t sbase, const __half* gbase,
                                          int K, int tid) {
#pragma unroll
    for (int i = 0; i < 4; i++) {
        int u = tid + 256 * i;            // 0..1023
        int row = u >> 3;
        int c = u & 7;
        const __half* src = gbase + (size_t)row * K + c * 8;
        uint32_t dst = sbase + SWZ((uint32_t)(row * BKB + c * 16));
        cp16(dst, src);
    }
}

// ========== GEMM 1-term (3-stage pipeline, ONE __syncthreads per chunk) =====
#define STG1 (2 * TILE_B)             // 32 KB per stage (A + B tiles)
#define NST 3
__global__ __launch_bounds__(256, 2) void gemm_1t(
    const __half* __restrict__ A, const __half* __restrict__ B,
    float* __restrict__ Cf, __half* __restrict__ Ch,
    int M, int N, int K) {
    extern __shared__ char sm[];
    const uint32_t sb = smem_u32(sm);
    const int tid = threadIdx.x, wid = tid >> 5, lane = tid & 31;
    const int m0 = blockIdx.y * 128, n0 = blockIdx.x * 128;
    const int wm = (wid & 1) * 64, wn = (wid >> 1) * 32;

    const __half* gA = A + (size_t)m0 * K;
    const __half* gB = B + (size_t)n0 * K;

    float acc[4][4][4];
#pragma unroll
    for (int i = 0; i < 4; i++)
#pragma unroll
        for (int j = 0; j < 4; j++)
#pragma unroll
            for (int q = 0; q < 4; q++) acc[i][j][q] = 0.f;

    const int NC = K / 64;

    // prologue: stages 0 and 1 (2 commit groups)
#pragma unroll
    for (int s = 0; s < 2; s++) {
        uint32_t st = sb + s * STG1;
        load_tile(st, gA + s * 64, K, tid);
        load_tile(st + TILE_B, gB + s * 64, K, tid);
        asm volatile("cp.async.commit_group;" ::: "memory");
    }

    const int lrow = lane & 15, lcol = (lane >> 4) * 16;
    int sidx = 0;

    for (int c = 0; c < NC; c++) {
        // ensure stage c is resident (keep the newer group in flight)
        if (c + 1 < NC) {
            asm volatile("cp.async.wait_group 1;" ::: "memory");
        } else {
            asm volatile("cp.async.wait_group 0;" ::: "memory");
        }
        __syncthreads();   // all warps done reading stage (c-1) == (c+2)%NST

        // refill stage (c+2)%NST — safe after the barrier above
        if (c + 2 < NC) {
            int s2 = sidx + 2; if (s2 >= NST) s2 -= NST;
            uint32_t st2 = sb + s2 * STG1;
            load_tile(st2, gA + (c + 2) * 64, K, tid);
            load_tile(st2 + TILE_B, gB + (c + 2) * 64, K, tid);
            asm volatile("cp.async.commit_group;" ::: "memory");
        }

        uint32_t st = sb + sidx * STG1;
#pragma unroll
        for (int ks = 0; ks < 4; ks++) {
            const int kb = ks * 32 + lcol;
            uint32_t ra[4][4], rb[2][4];
#pragma unroll
            for (int mi = 0; mi < 4; mi++) {
                int row = wm + mi * 16 + lrow;
                ldsm4(ra[mi], st + SWZ((uint32_t)(row * BKB + kb)));
            }
#pragma unroll
            for (int bj = 0; bj < 2; bj++) {
                int row = wn + bj * 16 + lrow;
                ldsm4(rb[bj], st + TILE_B + SWZ((uint32_t)(row * BKB + kb)));
            }
#pragma unroll
            for (int mi = 0; mi < 4; mi++)
#pragma unroll
                for (int nj = 0; nj < 4; nj++) {
                    uint32_t b0 = rb[nj >> 1][nj & 1];
                    uint32_t b1 = rb[nj >> 1][2 + (nj & 1)];
                    mma16816(acc[mi][nj], ra[mi], b0, b1);
                }
        }
        if (++sidx == NST) sidx = 0;
    }

    const int er = lane >> 2, ec = (lane & 3) * 2;
#pragma unroll
    for (int mi = 0; mi < 4; mi++)
#pragma unroll
        for (int nj = 0; nj < 4; nj++) {
            int col = n0 + wn + nj * 8 + ec;
            int row0 = m0 + wm + mi * 16 + er, row1 = row0 + 8;
            float2 v0 = make_float2(acc[mi][nj][0], acc[mi][nj][1]);
            float2 v1 = make_float2(acc[mi][nj][2], acc[mi][nj][3]);
            if (Cf) {
                *(float2*)(Cf + (size_t)row0 * N + col) = v0;
                *(float2*)(Cf + (size_t)row1 * N + col) = v1;
            }
            if (Ch) {
                uint32_t p0, p1;
                asm("cvt.rn.f16x2.f32 %0, %1, %2;" : "=r"(p0) : "f"(v0.y), "f"(v0.x));
                asm("cvt.rn.f16x2.f32 %0, %1, %2;" : "=r"(p1) : "f"(v1.y), "f"(v1.x));
                ((uint32_t*)Ch)[((size_t)row0 * N + col) >> 1] = p0;
                ((uint32_t*)Ch)[((size_t)row1 * N + col) >> 1] = p1;
            }
        }
}

// ====== GEMM 2-term, 64x64 tiles: Wc = A @ (Bh + Bl)^T (Wc precompute) ======
#define TB64 (64 * BKB)               // 8 KB per 64x64 fp16 tile
#define STG64B (3 * TB64)             // 24 KB per stage (A, Bh, Bl)
__global__ __launch_bounds__(128, 3) void gemm_2t_64(
    const __half* __restrict__ A,
    const __half* __restrict__ Bh, const __half* __restrict__ Bl,
    __half* __restrict__ Chalf, int M, int N, int K) {
    extern __shared__ char sm[];
    const uint32_t sb = smem_u32(sm);
    const int tid = threadIdx.x, wid = tid >> 5, lane = tid & 31;
    const int m0 = blockIdx.y * 64, n0 = blockIdx.x * 64;
    const int wm = (wid & 1) * 32, wn = (wid >> 1) * 32;

    const __half* gA  = A  + (size_t)m0 * K;
    const __half* gBh = Bh + (size_t)n0 * K;
    const __half* gBl = Bl + (size_t)n0 * K;

    float acc[2][4][4];
#pragma unroll
    for (int i = 0; i < 2; i++)
#pragma unroll
        for (int j = 0; j < 4; j++)
#pragma unroll
            for (int q = 0; q < 4; q++) acc[i][j][q] = 0.f;

    const int NC = K / 64;

    auto load64 = [&](uint32_t sbase, const __half* g, int k0) {
#pragma unroll
        for (int i = 0; i < 4; i++) {
            int u = tid + 128 * i;        // 0..511
            int row = u >> 3;
            int c = u & 7;
            cp16(sbase + SWZ((uint32_t)(row * BKB + c * 16)),
                 g + k0 + (size_t)row * K + c * 8);
        }
    };

    load64(sb, gA, 0);
    load64(sb + TB64, gBh, 0);
    load64(sb + 2 * TB64, gBl, 0);
    asm volatile("cp.async.commit_group;" ::: "memory");

    const int lrow = lane & 15, lcol = (lane >> 4) * 16;

    for (int c = 0; c < NC; c++) {
        if (c + 1 < NC) {
            uint32_t s1 = sb + ((c + 1) & 1) * STG64B;
            load64(s1, gA, (c + 1) * 64);
            load64(s1 + TB64, gBh, (c + 1) * 64);
            load64(s1 + 2 * TB64, gBl, (c + 1) * 64);
            asm volatile("cp.async.commit_group;" ::: "memory");
            asm volatile("cp.async.wait_group 1;" ::: "memory");
        } else {
            asm volatile("cp.async.wait_group 0;" ::: "memory");
        }
        __syncthreads();

        uint32_t st = sb + (c & 1) * STG64B;
#pragma unroll
        for (int ks = 0; ks < 4; ks++) {
            const int kb = ks * 32 + lcol;
            uint32_t ra[2][4], rbh[2][4], rbl[2][4];
#pragma unroll
            for (int mi = 0; mi < 2; mi++) {
                int row = wm + mi * 16 + lrow;
                ldsm4(ra[mi], st + SWZ((uint32_t)(row * BKB + kb)));
            }
#pragma unroll
            for (int bj = 0; bj < 2; bj++) {
                int row = wn + bj * 16 + lrow;
                ldsm4(rbh[bj], st + TB64 + SWZ((uint32_t)(row * BKB + kb)));
                ldsm4(rbl[bj], st + 2 * TB64 + SWZ((uint32_t)(row * BKB + kb)));
            }
#pragma unroll
            for (int mi = 0; mi < 2; mi++)
#pragma unroll
                for (int nj = 0; nj < 4; nj++) {
                    uint32_t b0 = rbh[nj >> 1][nj & 1];
                    uint32_t b1 = rbh[nj >> 1][2 + (nj & 1)];
                    mma16816(acc[mi][nj], ra[mi], b0, b1);
                }
#pragma unroll
            for (int mi = 0; mi < 2; mi++)
#pragma unroll
                for (int nj = 0; nj < 4; nj++) {
                    uint32_t b0 = rbl[nj >> 1][nj & 1];
                    uint32_t b1 = rbl[nj >> 1][2 + (nj & 1)];
                    mma16816(acc[mi][nj], ra[mi], b0, b1);
                }
        }
        __syncthreads();
    }

    const int er = lane >> 2, ec = (lane & 3) * 2;
#pragma unroll
    for (int mi = 0; mi < 2; mi++)
#pragma unroll
        for (int nj = 0; nj < 4; nj++) {
            int col = n0 + wn + nj * 8 + ec;
            int row0 = m0 + wm + mi * 16 + er, row1 = row0 + 8;
            uint32_t p0, p1;
            asm("cvt.rn.f16x2.f32 %0, %1, %2;" : "=r"(p0)
                : "f"(acc[mi][nj][1]), "f"(acc[mi][nj][0]));
            asm("cvt.rn.f16x2.f32 %0, %1, %2;" : "=r"(p1)
                : "f"(acc[mi][nj][3]), "f"(acc[mi][nj][2]));
            ((uint32_t*)Chalf)[((size_t)row0 * N + col) >> 1] = p0;
            ((uint32_t*)Chalf)[((size_t)row1 * N + col) >> 1] = p1;
        }
}

// =========================== recurrence (segmented) =========================
__device__ __forceinline__ float fast_tanh(float x) {
    float y;
    asm("tanh.approx.f32 %0, %1;" : "=f"(y) : "f"(x));
    return y;
}

#define SEGL 128
#define WARM 32
__global__ __launch_bounds__(128) void recurrence_seg(
    const __half* __restrict__ wide,   // fp16 [B*T, 2048]
    const float* __restrict__ h0, const float* __restrict__ alpha_raw,
    const float* __restrict__ bias, const float* __restrict__ bgate,
    __half* __restrict__ cell, float* __restrict__ hfin,
    int B, int T, int D, int nseg) {
    int idx = blockIdx.x * blockDim.x + threadIdx.x;
    if (idx >= B * nseg * D) return;
    int d   = idx % D;
    int t2  = idx / D;
    int seg = t2 % nseg;
    int bb  = t2 / nseg;

    float alpha = 1.f / (1.f + __expf(-alpha_raw[d]));
    float bv = bias[d];
    float bg = bgate[d];

    const int W2 = 2 * D;
    size_t rowbase = (size_t)bb * T * W2 + d;
    const int t0 = seg * SEGL;

    float h;
    if (seg == 0) {
        h = h0[bb * D + d];
    } else {
        h = 0.f;
#pragma unroll 4
        for (int t = t0 - WARM; t < t0; t++) {
            float xwv = __half2float(wide[rowbase + (size_t)t * W2 + D]);
            h = fast_tanh(fmaf(alpha, h, xwv + bv));
        }
    }

    size_t cbase = (size_t)bb * T * D + d;
#pragma unroll 4
    for (int t = t0; t < t0 + SEGL; t++) {
        float xpv = __half2float(wide[rowbase + (size_t)t * W2]);
        float xwv = __half2float(wide[rowbase + (size_t)t * W2 + D]);
        h = fast_tanh(fmaf(alpha, h, xwv + bv));
        float gt = xpv + bg;
        float sg = fmaf(0.5f, fast_tanh(0.5f * gt), 0.5f);   // sigmoid
        cell[cbase + (size_t)t * D] = __float2half_rn(h * (gt * sg));
    }
    if (hfin && seg == nseg - 1) hfin[bb * D + d] = h;
}

// ============================== launch ======================================
extern "C" void kernel_launch(void* const* d_in, const int* in_sizes, int n_in,
                              void* d_out, int out_size) {
    const float* x         = (const float*)d_in[0];
    const float* h0        = (const float*)d_in[1];
    const float* W_in      = (const float*)d_in[2];
    const float* W_x       = (const float*)d_in[3];
    const float* alpha_raw = (const float*)d_in[4];
    const float* b         = (const float*)d_in[5];
    const float* b_gate    = (const float*)d_in[6];
    const float* W_out     = (const float*)d_in[7];
    float* out = (float*)d_out;

    const int D   = in_sizes[4];          // 1024
    const int BD  = in_sizes[1];          // B*D
    const int Bn  = BD / D;               // 8
    const int BTD = in_sizes[0];          // B*T*D
    const int T   = BTD / BD;             // 2048
    const int M   = Bn * T;               // 16384

    __half *wide, *xh, *ch, *wfuse;
    __half *wxh, *with_, *witl, *woh;
    cudaGetSymbolAddress((void**)&wide, g_wide);
    cudaGetSymbolAddress((void**)&xh, g_xh);
    cudaGetSymbolAddress((void**)&ch, g_ch);
    cudaGetSymbolAddress((void**)&wfuse, g_wfuse);
    cudaGetSymbolAddress((void**)&wxh, g_wxh);
    cudaGetSymbolAddress((void**)&with_, g_with);
    cudaGetSymbolAddress((void**)&witl, g_witl);
    cudaGetSymbolAddress((void**)&woh, g_woh);

    cudaFuncSetAttribute(gemm_1t, cudaFuncAttributeMaxDynamicSharedMemorySize, NST * STG1);
    cudaFuncSetAttribute(gemm_2t_64, cudaFuncAttributeMaxDynamicSharedMemorySize, 2 * STG64B);

    const int w4 = (D * D) / 4;
    const int nx4 = BTD / 4;

    // 1) mega elementwise prep (x, W_x, W_out, W_in) in one launch
    {
        int total = nx4 + 3 * w4;
        prep_mega<<<(total + 255) / 256, 256>>>(x, W_x, W_out, W_in,
                                                xh, wxh, woh, wfuse, nx4, w4);
    }
    // 2) transpose-split of W_in
    {
        dim3 g(D / 32, D / 32);
        wsplit_t_kernel<<<g, 256>>>(W_in, with_, witl, D, D);
    }
    // 3) Wc = rn16(W_x) @ (W_in^T hi+lo) -> wfuse rows 1024..2047
    {
        dim3 g(D / 64, D / 64);
        gemm_2t_64<<<g, 128, 2 * STG64B>>>(wxh, with_, witl,
                                           wfuse + (size_t)D * D, D, D, D);
    }
    // 4) fused projection: [x_proj | xw] = x @ [Wi | Wc]^T  (fp16 out)
    {
        dim3 g((2 * D) / 128, M / 128);
        gemm_1t<<<g, 256, NST * STG1>>>(xh, wfuse, nullptr, wide, M, 2 * D, D);
    }
    // 5) segmented recurrence
    float* hfin = (out_size >= BTD + BD) ? (out + BTD) : nullptr;
    const int nseg = T / SEGL;
    {
        int total = Bn * nseg * D;
        recurrence_seg<<<(total + 127) / 128, 128>>>(
            wide, h0, alpha_raw, b, b_gate, ch, hfin, Bn, T, D, nseg);
    }
    // 6) output = cell @ W_out^T (single-term fp16)
    {
        dim3 g(D / 128, M / 128);
        gemm_1t<<<g, 256, NST * STG1>>>(ch, woh, out, nullptr, M, D, D);
    }
}

// round 13
// speedup vs baseline: 1.0360x; 1.0360x over previous
#include <cuda_runtime.h>
#include <cuda_fp16.h>
#include <stdint.h>

// ---------------------------------------------------------------------------
// DiagonalElman on GB300 (base sm_103 ISA: mma.sync fp16 + ldmatrix + cp.async)
// R12: gemm_1t rebalanced for smem-port pressure: 4 warps/CTA, warp tile
//  64x64 (ldsm:MMA 1:4), 128 threads, 2 CTAs/SM, 3-stage pipeline.
//  Wc = rn16(W_x) @ (W_in^T hi+lo) [2-term, 64x64 tiles],
//  fused [x_proj|xw] = x@[Wi|Wc]^T (1-term fp16), segmented recurrence,
//  output = cell @ W_out^T (1-term fp16). h_final at d_out + B*T*D.
// ---------------------------------------------------------------------------

#define MAX_BTD (8 * 2048 * 1024)
#define MAX_DD  (1024 * 1024)

__device__ __half g_wide[2 * MAX_BTD];        // fp16 [M,2048]: 0-1023 xp, 1024-2047 xw
__device__ __half g_xh[MAX_BTD];              // x as fp16
__device__ __half g_ch[MAX_BTD];              // cell_out as fp16
__device__ __half g_wfuse[2 * MAX_DD];        // [2048,1024]: rows 0-1023 Wi, 1024-2047 Wc
__device__ __half g_wxh[MAX_DD];              // rn16(W_x)
__device__ __half g_with[MAX_DD], g_witl[MAX_DD];   // split of W_in^T
__device__ __half g_woh[MAX_DD];

// ============================ helpers =======================================
__device__ __forceinline__ uint32_t smem_u32(const void* p) {
    uint32_t a;
    asm("{ .reg .u64 t; cvta.to.shared.u64 t, %1; cvt.u32.u64 %0, t; }"
        : "=r"(a) : "l"(p));
    return a;
}
#define SWZ(x) ((x) ^ (((x) >> 3) & 0x70))

// mega elementwise prep: one 1D grid covering 4 jobs by index range
__global__ __launch_bounds__(256) void prep_mega(
    const float* __restrict__ x, const float* __restrict__ W_x,
    const float* __restrict__ W_out, const float* __restrict__ W_in,
    __half* __restrict__ xh, __half* __restrict__ wxh,
    __half* __restrict__ woh, __half* __restrict__ wfuse,
    int nx4, int w4) {
    int i = blockIdx.x * blockDim.x + threadIdx.x;
    const float* src;
    __half* dst;
    int j;
    if (i < nx4)                      { src = x;     dst = xh;    j = i; }
    else if (i < nx4 + w4)            { src = W_x;   dst = wxh;   j = i - nx4; }
    else if (i < nx4 + 2 * w4)        { src = W_out; dst = woh;   j = i - nx4 - w4; }
    else if (i < nx4 + 3 * w4)        { src = W_in;  dst = wfuse; j = i - nx4 - 2 * w4; }
    else return;
    float4 v = ((const float4*)src)[j];
    __half h[4] = {__float2half_rn(v.x), __float2half_rn(v.y),
                   __float2half_rn(v.z), __float2half_rn(v.w)};
    ((uint64_t*)dst)[j] = *(const uint64_t*)h;
}

// transpose fp32 [R,C] and emit fp16 hi/lo split of the transpose
__global__ __launch_bounds__(256) void wsplit_t_kernel(
    const float* __restrict__ src, __half* __restrict__ hi,
    __half* __restrict__ lo, int R, int C) {
    __shared__ float tile[32][33];
    int bx = blockIdx.x * 32, by = blockIdx.y * 32;
    int tx = threadIdx.x & 31, ty8 = threadIdx.x >> 5;
#pragma unroll
    for (int r = 0; r < 32; r += 8) {
        int row = by + ty8 + r, col = bx + tx;
        if (row < R && col < C) tile[ty8 + r][tx] = src[(size_t)row * C + col];
    }
    __syncthreads();
#pragma unroll
    for (int r = 0; r < 32; r += 8) {
        int row = bx + ty8 + r, col = by + tx;
        if (row < C && col < R) {
            float v = tile[tx][ty8 + r];
            __half h = __float2half_rn(v);
            __half l = __float2half_rn(v - __half2float(h));
            hi[(size_t)row * R + col] = h;
            lo[(size_t)row * R + col] = l;
        }
    }
}

// ============================ GEMM common ===================================
#define BKB 128                       // bytes per smem row (64 fp16)
#define TILE_B (128 * BKB)            // 16 KB per 128x64 tile

__device__ __forceinline__ void cp16(uint32_t dst, const void* src) {
    asm volatile("cp.async.cg.shared.global [%0], [%1], 16;" :: "r"(dst), "l"(src));
}
__device__ __forceinline__ void ldsm4(uint32_t* r, uint32_t addr) {
    asm volatile("ldmatrix.sync.aligned.m8n8.x4.shared.b16 {%0,%1,%2,%3}, [%4];"
                 : "=r"(r[0]), "=r"(r[1]), "=r"(r[2]), "=r"(r[3]) : "r"(addr));
}
__device__ __forceinline__ void mma16816(float* c, const uint32_t* a, uint32_t b0, uint32_t b1) {
    asm volatile(
        "mma.sync.aligned.m16n8k16.row.col.f32.f16.f16.f32 "
        "{%0,%1,%2,%3}, {%4,%5,%6,%7}, {%8,%9}, {%0,%1,%2,%3};"
        : "+f"(c[0]), "+f"(c[1]), "+f"(c[2]), "+f"(c[3])
        : "r"(a[0]), "r"(a[1]), "r"(a[2]), "r"(a[3]), "r"(b0), "r"(b1));
}

// 128x64 tile loader for 128 threads (8 cp16 each)
__device__ __forceinline__ void load_tile128(uint32_t sbase, const __half* gbase,
                                             int K, int tid) {
#pragma unroll
    for (int i = 0; i < 8; i++) {
        int u = tid + 128 * i;            // 0..1023
        int row = u >> 3;
        int c = u & 7;
        const __half* src = gbase + (size_t)row * K + c * 8;
        uint32_t dst = sbase + SWZ((uint32_t)(row * BKB + c * 16));
        cp16(dst, src);
    }
}

// ===== GEMM 1-term: 4 warps, warp tile 64x64, 3-stage, 2 CTAs/SM ===========
#define STG1 (2 * TILE_B)             // 32 KB per stage (A + B tiles)
#define NST 3
__global__ __launch_bounds__(128, 2) void gemm_1t(
    const __half* __restrict__ A, const __half* __restrict__ B,
    float* __restrict__ Cf, __half* __restrict__ Ch,
    int M, int N, int K) {
    extern __shared__ char sm[];
    const uint32_t sb = smem_u32(sm);
    const int tid = threadIdx.x, wid = tid >> 5, lane = tid & 31;
    const int m0 = blockIdx.y * 128, n0 = blockIdx.x * 128;
    const int wm = (wid & 1) * 64, wn = (wid >> 1) * 64;

    const __half* gA = A + (size_t)m0 * K;
    const __half* gB = B + (size_t)n0 * K;

    float acc[4][8][4];
#pragma unroll
    for (int i = 0; i < 4; i++)
#pragma unroll
        for (int j = 0; j < 8; j++)
#pragma unroll
            for (int q = 0; q < 4; q++) acc[i][j][q] = 0.f;

    const int NC = K / 64;

    // prologue: stages 0 and 1
#pragma unroll
    for (int s = 0; s < 2; s++) {
        uint32_t st = sb + s * STG1;
        load_tile128(st, gA + s * 64, K, tid);
        load_tile128(st + TILE_B, gB + s * 64, K, tid);
        asm volatile("cp.async.commit_group;" ::: "memory");
    }

    const int lrow = lane & 15, lcol = (lane >> 4) * 16;
    int sidx = 0;

    for (int c = 0; c < NC; c++) {
        if (c + 1 < NC) {
            asm volatile("cp.async.wait_group 1;" ::: "memory");
        } else {
            asm volatile("cp.async.wait_group 0;" ::: "memory");
        }
        __syncthreads();

        // refill stage (c+2)%NST
        if (c + 2 < NC) {
            int s2 = sidx + 2; if (s2 >= NST) s2 -= NST;
            uint32_t st2 = sb + s2 * STG1;
            load_tile128(st2, gA + (c + 2) * 64, K, tid);
            load_tile128(st2 + TILE_B, gB + (c + 2) * 64, K, tid);
            asm volatile("cp.async.commit_group;" ::: "memory");
        }

        uint32_t st = sb + sidx * STG1;
#pragma unroll
        for (int ks = 0; ks < 4; ks++) {
            const int kb = ks * 32 + lcol;
            uint32_t ra[4][4], rb[4][4];
#pragma unroll
            for (int mi = 0; mi < 4; mi++) {
                int row = wm + mi * 16 + lrow;
                ldsm4(ra[mi], st + SWZ((uint32_t)(row * BKB + kb)));
            }
#pragma unroll
            for (int bj = 0; bj < 4; bj++) {
                int row = wn + bj * 16 + lrow;
                ldsm4(rb[bj], st + TILE_B + SWZ((uint32_t)(row * BKB + kb)));
            }
#pragma unroll
            for (int mi = 0; mi < 4; mi++)
#pragma unroll
                for (int nj = 0; nj < 8; nj++) {
                    uint32_t b0 = rb[nj >> 1][nj & 1];
                    uint32_t b1 = rb[nj >> 1][2 + (nj & 1)];
                    mma16816(acc[mi][nj], ra[mi], b0, b1);
                }
        }
        if (++sidx == NST) sidx = 0;
    }

    const int er = lane >> 2, ec = (lane & 3) * 2;
#pragma unroll
    for (int mi = 0; mi < 4; mi++)
#pragma unroll
        for (int nj = 0; nj < 8; nj++) {
            int col = n0 + wn + nj * 8 + ec;
            int row0 = m0 + wm + mi * 16 + er, row1 = row0 + 8;
            float2 v0 = make_float2(acc[mi][nj][0], acc[mi][nj][1]);
            float2 v1 = make_float2(acc[mi][nj][2], acc[mi][nj][3]);
            if (Cf) {
                *(float2*)(Cf + (size_t)row0 * N + col) = v0;
                *(float2*)(Cf + (size_t)row1 * N + col) = v1;
            }
            if (Ch) {
                uint32_t p0, p1;
                asm("cvt.rn.f16x2.f32 %0, %1, %2;" : "=r"(p0) : "f"(v0.y), "f"(v0.x));
                asm("cvt.rn.f16x2.f32 %0, %1, %2;" : "=r"(p1) : "f"(v1.y), "f"(v1.x));
                ((uint32_t*)Ch)[((size_t)row0 * N + col) >> 1] = p0;
                ((uint32_t*)Ch)[((size_t)row1 * N + col) >> 1] = p1;
            }
        }
}

// ====== GEMM 2-term, 64x64 tiles: Wc = A @ (Bh + Bl)^T (Wc precompute) ======
#define TB64 (64 * BKB)               // 8 KB per 64x64 fp16 tile
#define STG64B (3 * TB64)             // 24 KB per stage (A, Bh, Bl)
__global__ __launch_bounds__(128, 3) void gemm_2t_64(
    const __half* __restrict__ A,
    const __half* __restrict__ Bh, const __half* __restrict__ Bl,
    __half* __restrict__ Chalf, int M, int N, int K) {
    extern __shared__ char sm[];
    const uint32_t sb = smem_u32(sm);
    const int tid = threadIdx.x, wid = tid >> 5, lane = tid & 31;
    const int m0 = blockIdx.y * 64, n0 = blockIdx.x * 64;
    const int wm = (wid & 1) * 32, wn = (wid >> 1) * 32;

    const __half* gA  = A  + (size_t)m0 * K;
    const __half* gBh = Bh + (size_t)n0 * K;
    const __half* gBl = Bl + (size_t)n0 * K;

    float acc[2][4][4];
#pragma unroll
    for (int i = 0; i < 2; i++)
#pragma unroll
        for (int j = 0; j < 4; j++)
#pragma unroll
            for (int q = 0; q < 4; q++) acc[i][j][q] = 0.f;

    const int NC = K / 64;

    auto load64 = [&](uint32_t sbase, const __half* g, int k0) {
#pragma unroll
        for (int i = 0; i < 4; i++) {
            int u = tid + 128 * i;        // 0..511
            int row = u >> 3;
            int c = u & 7;
            cp16(sbase + SWZ((uint32_t)(row * BKB + c * 16)),
                 g + k0 + (size_t)row * K + c * 8);
        }
    };

    load64(sb, gA, 0);
    load64(sb + TB64, gBh, 0);
    load64(sb + 2 * TB64, gBl, 0);
    asm volatile("cp.async.commit_group;" ::: "memory");

    const int lrow = lane & 15, lcol = (lane >> 4) * 16;

    for (int c = 0; c < NC; c++) {
        if (c + 1 < NC) {
            uint32_t s1 = sb + ((c + 1) & 1) * STG64B;
            load64(s1, gA, (c + 1) * 64);
            load64(s1 + TB64, gBh, (c + 1) * 64);
            load64(s1 + 2 * TB64, gBl, (c + 1) * 64);
            asm volatile("cp.async.commit_group;" ::: "memory");
            asm volatile("cp.async.wait_group 1;" ::: "memory");
        } else {
            asm volatile("cp.async.wait_group 0;" ::: "memory");
        }
        __syncthreads();

        uint32_t st = sb + (c & 1) * STG64B;
#pragma unroll
        for (int ks = 0; ks < 4; ks++) {
            const int kb = ks * 32 + lcol;
            uint32_t ra[2][4], rbh[2][4], rbl[2][4];
#pragma unroll
            for (int mi = 0; mi < 2; mi++) {
                int row = wm + mi * 16 + lrow;
                ldsm4(ra[mi], st + SWZ((uint32_t)(row * BKB + kb)));
            }
#pragma unroll
            for (int bj = 0; bj < 2; bj++) {
                int row = wn + bj * 16 + lrow;
                ldsm4(rbh[bj], st + TB64 + SWZ((uint32_t)(row * BKB + kb)));
                ldsm4(rbl[bj], st + 2 * TB64 + SWZ((uint32_t)(row * BKB + kb)));
            }
#pragma unroll
            for (int mi = 0; mi < 2; mi++)
#pragma unroll
                for (int nj = 0; nj < 4; nj++) {
                    uint32_t b0 = rbh[nj >> 1][nj & 1];
                    uint32_t b1 = rbh[nj >> 1][2 + (nj & 1)];
                    mma16816(acc[mi][nj], ra[mi], b0, b1);
                }
#pragma unroll
            for (int mi = 0; mi < 2; mi++)
#pragma unroll
                for (int nj = 0; nj < 4; nj++) {
                    uint32_t b0 = rbl[nj >> 1][nj & 1];
                    uint32_t b1 = rbl[nj >> 1][2 + (nj & 1)];
                    mma16816(acc[mi][nj], ra[mi], b0, b1);
                }
        }
        __syncthreads();
    }

    const int er = lane >> 2, ec = (lane & 3) * 2;
#pragma unroll
    for (int mi = 0; mi < 2; mi++)
#pragma unroll
        for (int nj = 0; nj < 4; nj++) {
            int col = n0 + wn + nj * 8 + ec;
            int row0 = m0 + wm + mi * 16 + er, row1 = row0 + 8;
            uint32_t p0, p1;
            asm("cvt.rn.f16x2.f32 %0, %1, %2;" : "=r"(p0)
                : "f"(acc[mi][nj][1]), "f"(acc[mi][nj][0]));
            asm("cvt.rn.f16x2.f32 %0, %1, %2;" : "=r"(p1)
                : "f"(acc[mi][nj][3]), "f"(acc[mi][nj][2]));
            ((uint32_t*)Chalf)[((size_t)row0 * N + col) >> 1] = p0;
            ((uint32_t*)Chalf)[((size_t)row1 * N + col) >> 1] = p1;
        }
}

// =========================== recurrence (segmented) =========================
__device__ __forceinline__ float fast_tanh(float x) {
    float y;
    asm("tanh.approx.f32 %0, %1;" : "=f"(y) : "f"(x));
    return y;
}

#define SEGL 128
#define WARM 32
__global__ __launch_bounds__(128) void recurrence_seg(
    const __half* __restrict__ wide,   // fp16 [B*T, 2048]
    const float* __restrict__ h0, const float* __restrict__ alpha_raw,
    const float* __restrict__ bias, const float* __restrict__ bgate,
    __half* __restrict__ cell, float* __restrict__ hfin,
    int B, int T, int D, int nseg) {
    int idx = blockIdx.x * blockDim.x + threadIdx.x;
    if (idx >= B * nseg * D) return;
    int d   = idx % D;
    int t2  = idx / D;
    int seg = t2 % nseg;
    int bb  = t2 / nseg;

    float alpha = 1.f / (1.f + __expf(-alpha_raw[d]));
    float bv = bias[d];
    float bg = bgate[d];

    const int W2 = 2 * D;
    size_t rowbase = (size_t)bb * T * W2 + d;
    const int t0 = seg * SEGL;

    float h;
    if (seg == 0) {
        h = h0[bb * D + d];
    } else {
        h = 0.f;
#pragma unroll 4
        for (int t = t0 - WARM; t < t0; t++) {
            float xwv = __half2float(wide[rowbase + (size_t)t * W2 + D]);
            h = fast_tanh(fmaf(alpha, h, xwv + bv));
        }
    }

    size_t cbase = (size_t)bb * T * D + d;
#pragma unroll 4
    for (int t = t0; t < t0 + SEGL; t++) {
        float xpv = __half2float(wide[rowbase + (size_t)t * W2]);
        float xwv = __half2float(wide[rowbase + (size_t)t * W2 + D]);
        h = fast_tanh(fmaf(alpha, h, xwv + bv));
        float gt = xpv + bg;
        float sg = fmaf(0.5f, fast_tanh(0.5f * gt), 0.5f);   // sigmoid
        cell[cbase + (size_t)t * D] = __float2half_rn(h * (gt * sg));
    }
    if (hfin && seg == nseg - 1) hfin[bb * D + d] = h;
}

// ============================== launch ======================================
extern "C" void kernel_launch(void* const* d_in, const int* in_sizes, int n_in,
                              void* d_out, int out_size) {
    const float* x         = (const float*)d_in[0];
    const float* h0        = (const float*)d_in[1];
    const float* W_in      = (const float*)d_in[2];
    const float* W_x       = (const float*)d_in[3];
    const float* alpha_raw = (const float*)d_in[4];
    const float* b         = (const float*)d_in[5];
    const float* b_gate    = (const float*)d_in[6];
    const float* W_out     = (const float*)d_in[7];
    float* out = (float*)d_out;

    const int D   = in_sizes[4];          // 1024
    const int BD  = in_sizes[1];          // B*D
    const int Bn  = BD / D;               // 8
    const int BTD = in_sizes[0];          // B*T*D
    const int T   = BTD / BD;             // 2048
    const int M   = Bn * T;               // 16384

    __half *wide, *xh, *ch, *wfuse;
    __half *wxh, *with_, *witl, *woh;
    cudaGetSymbolAddress((void**)&wide, g_wide);
    cudaGetSymbolAddress((void**)&xh, g_xh);
    cudaGetSymbolAddress((void**)&ch, g_ch);
    cudaGetSymbolAddress((void**)&wfuse, g_wfuse);
    cudaGetSymbolAddress((void**)&wxh, g_wxh);
    cudaGetSymbolAddress((void**)&with_, g_with);
    cudaGetSymbolAddress((void**)&witl, g_witl);
    cudaGetSymbolAddress((void**)&woh, g_woh);

    cudaFuncSetAttribute(gemm_1t, cudaFuncAttributeMaxDynamicSharedMemorySize, NST * STG1);
    cudaFuncSetAttribute(gemm_2t_64, cudaFuncAttributeMaxDynamicSharedMemorySize, 2 * STG64B);

    const int w4 = (D * D) / 4;
    const int nx4 = BTD / 4;

    // 1) mega elementwise prep (x, W_x, W_out, W_in) in one launch
    {
        int total = nx4 + 3 * w4;
        prep_mega<<<(total + 255) / 256, 256>>>(x, W_x, W_out, W_in,
                                                xh, wxh, woh, wfuse, nx4, w4);
    }
    // 2) transpose-split of W_in
    {
        dim3 g(D / 32, D / 32);
        wsplit_t_kernel<<<g, 256>>>(W_in, with_, witl, D, D);
    }
    // 3) Wc = rn16(W_x) @ (W_in^T hi+lo) -> wfuse rows 1024..2047
    {
        dim3 g(D / 64, D / 64);
        gemm_2t_64<<<g, 128, 2 * STG64B>>>(wxh, with_, witl,
                                           wfuse + (size_t)D * D, D, D, D);
    }
    // 4) fused projection: [x_proj | xw] = x @ [Wi | Wc]^T  (fp16 out)
    {
        dim3 g((2 * D) / 128, M / 128);
        gemm_1t<<<g, 128, NST * STG1>>>(xh, wfuse, nullptr, wide, M, 2 * D, D);
    }
    // 5) segmented recurrence
    float* hfin = (out_size >= BTD + BD) ? (out + BTD) : nullptr;
    const int nseg = T / SEGL;
    {
        int total = Bn * nseg * D;
        recurrence_seg<<<(total + 127) / 128, 128>>>(
            wide, h0, alpha_raw, b, b_gate, ch, hfin, Bn, T, D, nseg);
    }
    // 6) output = cell @ W_out^T (single-term fp16)
    {
        dim3 g(D / 128, M / 128);
        gemm_1t<<<g, 128, NST * STG1>>>(ch, woh, out, nullptr, M, D, D);
    }
}